// round 14
// baseline (speedup 1.0000x reference)
#include <cuda_runtime.h>
#include <cuda_fp16.h>
#include <cstdint>

#define B 32
#define N 1024
#define M 1024
#define TOL 0.001f
#define MAX_ITER 50
#define GRID 256               // 8 blocks/batch; 2 blocks/SM co-resident
#define TPB 512
#define RPB 128                // rows per block
#define EM105 2.7536449349747158e-5f   // exp(-10.5): scaled-u init (log_u0 = 0)

// ---------------------------------------------------------------------------
__device__ __half   g_K16[(size_t)B * N * M];    // 64 MB: e^10.5*exp(-20c), L2-resident
__device__ float    g_partial[2 * GRID * M];     // double-buffered col partials
__device__ int      g_change[MAX_ITER];          // per-iter max |dlog u| (float bits)
__device__ unsigned g_barCount;
__device__ unsigned g_barGen;

__global__ void initKernel() {
    int i = threadIdx.x;
    if (i < MAX_ITER) g_change[i] = 0;
    if (i == 0) { g_barCount = 0u; g_barGen = 0u; }
}

__device__ __forceinline__ float dot8(uint4 kq, float4 va, float4 vb) {
    float2 f0 = __half22float2(*(__half2*)&kq.x);
    float2 f1 = __half22float2(*(__half2*)&kq.y);
    float2 f2 = __half22float2(*(__half2*)&kq.z);
    float2 f3 = __half22float2(*(__half2*)&kq.w);
    return f0.x*va.x + f0.y*va.y + f1.x*va.z + f1.y*va.w
         + f2.x*vb.x + f2.y*vb.y + f3.x*vb.z + f3.y*vb.w;
}

// Named producer/consumer barriers (ids 1..8; id 0 reserved for __syncthreads)
__device__ __forceinline__ void barArrive(int id) {
    asm volatile("bar.arrive %0, %1;" :: "r"(id), "r"(TPB) : "memory");
}
__device__ __forceinline__ void barWait(int id) {
    asm volatile("bar.sync %0, %1;" :: "r"(id), "r"(TPB) : "memory");
}

__device__ __forceinline__ void gridBarrier(unsigned gen) {
    __syncthreads();
    if (threadIdx.x == 0) {
        __threadfence();
        if (atomicAdd(&g_barCount, 1u) == GRID - 1) {
            atomicExch(&g_barCount, 0u);
            __threadfence();
            atomicExch(&g_barGen, gen + 1u);
        } else {
            while (atomicAdd(&g_barGen, 0u) < gen + 1u) { __nanosleep(64); }
        }
        __threadfence();
    }
    __syncthreads();
}

// ---------------------------------------------------------------------------
// Persistent fused Sinkhorn, warp-specialized iteration sweep.
//  prologue: convert cost->K16 (MUFU expf) per 16-row group with smem staging;
//            computes u1 per row (shuffle sum, v0=1) AND iteration-0 col acc.
//  it>=1:    warps 0-7 free-run row dots (L2) over 8 x 16-row groups, arriving
//            on named barrier g+1; warps 8-15 col-acc group g from L1 after
//            bar.sync(g+1). Zero __syncthreads inside the sweep.
//  tail:     stage col partials -> block partial -> 1 grid barrier -> v -> check.
//  epilogue: T = u' * K16 * v (streaming stores).
// ---------------------------------------------------------------------------
__global__ void __launch_bounds__(TPB, 2) sinkhornKernel(
    const float* __restrict__ cost, const float* __restrict__ src,
    const float* __restrict__ tgt, float* __restrict__ out) {

    __shared__ float sv[M];                        // v for this batch
    __shared__ __align__(16) char sbuf[16 * M * 2];// 32KB union: stage / sacc
    __shared__ float suAll[RPB];                   // scaled u' for block's rows
    __shared__ float ssrc[RPB];                    // src + 1e-12, cached
    __shared__ float schg[16];

    __half (*stage)[M] = (__half(*)[M])sbuf;       // [16][1024] halves (32KB)
    float  (*sacc)[M]  = (float (*)[M])sbuf;       // [<=4][1024] floats

    const int t    = threadIdx.x;
    const int w    = t >> 5;
    const int lane = t & 31;
    const int blk  = blockIdx.x;
    const int b    = blk >> 3;
    const int sl   = blk & 7;
    const int rowBase = (b << 10) + (sl << 7);
    const size_t elemBase = (size_t)rowBase << 10;

    const float4* sv4 = (const float4*)sv;

    if (t < RPB) ssrc[t] = __ldg(src + rowBase + t) + 1e-12f;
    __syncthreads();

    // ---- prologue: conversion fused with u1 + iteration-0 col acc ----
    {
        const int cg = t & 127, rs = t >> 7;       // col-acc layout (4 subsets)
        float accv[8];
        #pragma unroll
        for (int j = 0; j < 8; ++j) accv[j] = 0.f;
        float chm = 0.f;

        const float4* Cb = (const float4*)(cost + elemBase);
        for (int g = 0; g < 8; ++g) {              // 16-row groups
            int r = (g << 4) + w;                  // warp w owns row r (16 warps)
            const float4* Cr = Cb + ((size_t)r << 8);
            uint4* Kw = (uint4*)(g_K16 + elemBase + ((size_t)r << 10));
            uint4* Sw = (uint4*)stage[w];
            float s = 0.f;
            #pragma unroll
            for (int i = 0; i < 4; ++i) {
                int idx = i * 32 + lane;
                float4 c0 = __ldcs(&Cr[2 * idx]);
                float4 c1 = __ldcs(&Cr[2 * idx + 1]);
                float f0 = __expf(fmaf(c0.x, -20.f, 10.5f));
                float f1 = __expf(fmaf(c0.y, -20.f, 10.5f));
                float f2 = __expf(fmaf(c0.z, -20.f, 10.5f));
                float f3 = __expf(fmaf(c0.w, -20.f, 10.5f));
                float f4 = __expf(fmaf(c1.x, -20.f, 10.5f));
                float f5 = __expf(fmaf(c1.y, -20.f, 10.5f));
                float f6 = __expf(fmaf(c1.z, -20.f, 10.5f));
                float f7 = __expf(fmaf(c1.w, -20.f, 10.5f));
                s += ((f0 + f1) + (f2 + f3)) + ((f4 + f5) + (f6 + f7));
                __half2 h0 = __floats2half2_rn(f0, f1);
                __half2 h1 = __floats2half2_rn(f2, f3);
                __half2 h2 = __floats2half2_rn(f4, f5);
                __half2 h3 = __floats2half2_rn(f6, f7);
                uint4 pk;
                pk.x = *(unsigned*)&h0; pk.y = *(unsigned*)&h1;
                pk.z = *(unsigned*)&h2; pk.w = *(unsigned*)&h3;
                Kw[idx] = pk;
                Sw[idx] = pk;
            }
            #pragma unroll
            for (int o = 16; o; o >>= 1) s += __shfl_xor_sync(~0u, s, o);
            if (lane == 0) {
                float nu = ssrc[r] / s;            // v0 = 1 => rowdot = rowsum
                suAll[r] = nu;
                chm = fmaxf(chm, fabsf(logf(nu / EM105)));
            }
            __syncthreads();
            // it-0 col acc from staged halves (bit-identical to K16)
            #pragma unroll
            for (int j = 0; j < 4; ++j) {
                int rr = (rs << 2) + j;
                uint4 kq = ((const uint4*)stage[rr])[cg];
                float uu = suAll[(g << 4) + rr];
                float2 a  = __half22float2(*(__half2*)&kq.x);
                float2 bb = __half22float2(*(__half2*)&kq.y);
                float2 cc = __half22float2(*(__half2*)&kq.z);
                float2 dd = __half22float2(*(__half2*)&kq.w);
                accv[0] = fmaf(a.x,  uu, accv[0]);
                accv[1] = fmaf(a.y,  uu, accv[1]);
                accv[2] = fmaf(bb.x, uu, accv[2]);
                accv[3] = fmaf(bb.y, uu, accv[3]);
                accv[4] = fmaf(cc.x, uu, accv[4]);
                accv[5] = fmaf(cc.y, uu, accv[5]);
                accv[6] = fmaf(dd.x, uu, accv[6]);
                accv[7] = fmaf(dd.y, uu, accv[7]);
            }
            __syncthreads();
        }

        // tail for it = 0 (4 row-subsets)
        #pragma unroll
        for (int j = 0; j < 8; ++j) sacc[rs][cg * 8 + j] = accv[j];
        if (lane == 0) schg[w] = chm;
        __syncthreads();
        {
            float* pp = g_partial + (size_t)blk * M;   // parity 0
            #pragma unroll
            for (int c = t; c < M; c += TPB)
                pp[c] = (sacc[0][c] + sacc[1][c]) + (sacc[2][c] + sacc[3][c]);
        }
        if (t == 0) {
            float m = schg[0];
            #pragma unroll
            for (int i = 1; i < 16; ++i) m = fmaxf(m, schg[i]);
            atomicMax(&g_change[0], __float_as_int(m));
        }
    }

    unsigned gen = 0;
    gridBarrier(gen); ++gen;

    // v-phase for it = 0
    {
        const float* pb = g_partial + ((size_t)(b << 3)) * M;
        #pragma unroll
        for (int c = t; c < M; c += TPB) {
            float ssum = 0.f;
            #pragma unroll
            for (int k = 0; k < 8; ++k) ssum += __ldcg(pb + k * M + c);
            sv[c] = (__ldg(tgt + (b << 10) + c) + 1e-12f) / ssum;
        }
    }
    float ch0 = __int_as_float(__ldcg(&g_change[0]));
    __syncthreads();

    if (ch0 >= TOL) {
        for (int it = 1; it < MAX_ITER; ++it) {
            // ---- warp-specialized sweep: zero __syncthreads inside ----
            if (w < 8) {
                // row warps: free-run 8 groups of 16 rows (2 rows per warp)
                float chm = 0.f;
                for (int g = 0; g < 8; ++g) {
                    int r0 = (g << 4) + (w << 1);
                    const uint4* K0 = (const uint4*)g_K16
                                      + ((size_t)(rowBase + r0) << 7);
                    float s0 = 0.f, s1 = 0.f;
                    #pragma unroll
                    for (int i = 0; i < 4; ++i) {
                        int ci = i * 32 + lane;
                        uint4 ka = K0[ci], kb = K0[128 + ci];
                        float4 va = sv4[2 * ci], vb = sv4[2 * ci + 1];
                        s0 += dot8(ka, va, vb);
                        s1 += dot8(kb, va, vb);
                    }
                    #pragma unroll
                    for (int o = 16; o; o >>= 1) {
                        s0 += __shfl_xor_sync(~0u, s0, o);
                        s1 += __shfl_xor_sync(~0u, s1, o);
                    }
                    if (lane == 0) {
                        float o0 = suAll[r0], o1 = suAll[r0 + 1];
                        float n0 = ssrc[r0]     / s0;
                        float n1 = ssrc[r0 + 1] / s1;
                        suAll[r0] = n0; suAll[r0 + 1] = n1;
                        chm = fmaxf(chm,
                              fmaxf(fabsf(logf(n0 / o0)), fabsf(logf(n1 / o1))));
                    }
                    barArrive(g + 1);              // publish group g's u
                }
                #pragma unroll
                for (int o = 16; o; o >>= 1)
                    chm = fmaxf(chm, __shfl_xor_sync(~0u, chm, o));
                if (lane == 0) schg[w] = chm;
            } else {
                // col warps: consume groups as they land (L1-hot)
                const int tc = t - 256;            // 0..255
                const int cg = tc & 127, rs = tc >> 7;
                float accv[8];
                #pragma unroll
                for (int j = 0; j < 8; ++j) accv[j] = 0.f;
                for (int g = 0; g < 8; ++g) {
                    barWait(g + 1);                // u + K lines of group g ready
                    int rr0 = (g << 4) + (rs << 3);
                    const uint4* Kc = (const uint4*)g_K16
                        + ((size_t)(rowBase + rr0) << 7) + cg;
                    #pragma unroll
                    for (int j = 0; j < 8; ++j) {
                        uint4 kq = Kc[(size_t)j << 7];
                        float uu = suAll[rr0 + j];
                        float2 a  = __half22float2(*(__half2*)&kq.x);
                        float2 bb = __half22float2(*(__half2*)&kq.y);
                        float2 cc = __half22float2(*(__half2*)&kq.z);
                        float2 dd = __half22float2(*(__half2*)&kq.w);
                        accv[0] = fmaf(a.x,  uu, accv[0]);
                        accv[1] = fmaf(a.y,  uu, accv[1]);
                        accv[2] = fmaf(bb.x, uu, accv[2]);
                        accv[3] = fmaf(bb.y, uu, accv[3]);
                        accv[4] = fmaf(cc.x, uu, accv[4]);
                        accv[5] = fmaf(cc.y, uu, accv[5]);
                        accv[6] = fmaf(dd.x, uu, accv[6]);
                        accv[7] = fmaf(dd.y, uu, accv[7]);
                    }
                }
                #pragma unroll
                for (int j = 0; j < 8; ++j) sacc[rs][cg * 8 + j] = accv[j];
            }
            __syncthreads();

            // ---- tail: combine 2 subsets -> block partial; publish change ----
            {
                float* pp = g_partial + ((size_t)(it & 1) * GRID + blk) * M;
                #pragma unroll
                for (int c = t; c < M; c += TPB)
                    pp[c] = sacc[0][c] + sacc[1][c];
            }
            if (t == 0) {
                float m = schg[0];
                #pragma unroll
                for (int i = 1; i < 8; ++i) m = fmaxf(m, schg[i]);
                atomicMax(&g_change[it], __float_as_int(m));
            }

            gridBarrier(gen); ++gen;

            // ---- v-phase: every block of batch b builds full v ----
            {
                const float* pb = g_partial
                    + ((size_t)(it & 1) * GRID + (b << 3)) * M;
                #pragma unroll
                for (int c = t; c < M; c += TPB) {
                    float ssum = 0.f;
                    #pragma unroll
                    for (int k = 0; k < 8; ++k) ssum += __ldcg(pb + k * M + c);
                    sv[c] = (__ldg(tgt + (b << 10) + c) + 1e-12f) / ssum;
                }
            }
            float ch = __int_as_float(__ldcg(&g_change[it]));
            __syncthreads();        // sv complete before next iter / epilogue
            if (ch < TOL) break;    // uniform across grid
        }
    }

    // ---- epilogue: T = u' * K16 * v (K16 from L2, streaming stores) ----
    {
        const uint4* Kr = (const uint4*)(g_K16 + elemBase);
        float4* Ow = (float4*)(out + elemBase);
        #pragma unroll 2
        for (int k = 0; k < 32; ++k) {
            int i = k * TPB + t;                   // uint4 idx in 128x1024 slice
            uint4 kq = Kr[i];
            float u = suAll[i >> 7];
            float4 va = sv4[(i & 127) * 2], vb = sv4[(i & 127) * 2 + 1];
            float2 f0 = __half22float2(*(__half2*)&kq.x);
            float2 f1 = __half22float2(*(__half2*)&kq.y);
            float2 f2 = __half22float2(*(__half2*)&kq.z);
            float2 f3 = __half22float2(*(__half2*)&kq.w);
            float4 o0, o1;
            o0.x = u * f0.x * va.x;
            o0.y = u * f0.y * va.y;
            o0.z = u * f1.x * va.z;
            o0.w = u * f1.y * va.w;
            o1.x = u * f2.x * vb.x;
            o1.y = u * f2.y * vb.y;
            o1.z = u * f3.x * vb.z;
            o1.w = u * f3.y * vb.w;
            __stcs(Ow + 2 * i,     o0);
            __stcs(Ow + 2 * i + 1, o1);
        }
    }
}

// ---------------------------------------------------------------------------
extern "C" void kernel_launch(void* const* d_in, const int* in_sizes, int n_in,
                              void* d_out, int out_size) {
    const float* cost = (const float*)d_in[0];
    const float* src  = (const float*)d_in[1];
    const float* tgt  = (const float*)d_in[2];
    float* out = (float*)d_out;

    initKernel<<<1, 64>>>();
    sinkhornKernel<<<GRID, TPB>>>(cost, src, tgt, out);
}

// round 15
// speedup vs baseline: 1.0303x; 1.0303x over previous
#include <cuda_runtime.h>
#include <cuda_fp16.h>
#include <cstdint>

#define B 32
#define N 1024
#define M 1024
#define TOL 0.001f
#define MAX_ITER 50
#define GRID 256               // 8 blocks/batch; 2 blocks/SM co-resident
#define TPB 512
#define RPB 128                // rows per block
#define EM105 2.7536449349747158e-5f   // exp(-10.5): scaled-u init (log_u0 = 0)

// ---------------------------------------------------------------------------
__device__ __half   g_K16[(size_t)B * N * M];    // 64 MB: e^10.5*exp(-20c), L2-resident
__device__ float    g_partial[2 * GRID * M];     // double-buffered col partials
__device__ int      g_change[MAX_ITER];          // per-iter max |dlog u| (float bits)
__device__ unsigned g_batArrive[B * 32];         // per-batch arrival (1 line each)
__device__ unsigned g_barCount;                  // batch-leader count
__device__ unsigned g_barGen;                    // release generation

__global__ void initKernel() {
    int i = threadIdx.x;
    for (int k = i; k < MAX_ITER; k += 256) g_change[k] = 0;
    for (int k = i; k < B * 32; k += 256) g_batArrive[k] = 0u;
    if (i == 0) { g_barCount = 0u; g_barGen = 0u; }
}

__device__ __forceinline__ float dot8(uint4 kq, float4 va, float4 vb) {
    float2 f0 = __half22float2(*(__half2*)&kq.x);
    float2 f1 = __half22float2(*(__half2*)&kq.y);
    float2 f2 = __half22float2(*(__half2*)&kq.z);
    float2 f3 = __half22float2(*(__half2*)&kq.w);
    return f0.x*va.x + f0.y*va.y + f1.x*va.z + f1.y*va.w
         + f2.x*vb.x + f2.y*vb.y + f3.x*vb.z + f3.y*vb.w;
}

// Hierarchical grid barrier: 8 arrivals/batch line -> 32 leaders -> release.
// Spin is a volatile LOAD (L2 read throughput), never an atomic.
__device__ __forceinline__ void gridBarrier(int b, unsigned gen) {
    __syncthreads();
    if (threadIdx.x == 0) {
        __threadfence();
        unsigned a = atomicAdd(&g_batArrive[b * 32], 1u);
        if (a == 7u) {                               // last block of batch b
            atomicExch(&g_batArrive[b * 32], 0u);    // safe: all 8 arrived
            unsigned g = atomicAdd(&g_barCount, 1u);
            if (g == (unsigned)(B - 1)) {            // last batch
                atomicExch(&g_barCount, 0u);
                __threadfence();
                atomicExch(&g_barGen, gen + 1u);
            }
        }
        while (*(volatile unsigned*)&g_barGen < gen + 1u) __nanosleep(32);
        __threadfence();
    }
    __syncthreads();
}

// ---------------------------------------------------------------------------
// Persistent fused Sinkhorn (R12 structure).
//  prologue: convert cost->K16 (MUFU expf) per 16-row group with smem staging;
//            computes u1 per row (shuffle sum, v0=1) AND iteration-0 col acc.
//  it>=1:    unified sweep: all 16 warps row-dot (L2), then col-acc (L1),
//            per 32-row group.
//  tail:     stage col partials -> block partial -> 1 grid barrier -> v -> check.
//  epilogue: T = u' * K16 * v (streaming stores).
// ---------------------------------------------------------------------------
__global__ void __launch_bounds__(TPB, 2) sinkhornKernel(
    const float* __restrict__ cost, const float* __restrict__ src,
    const float* __restrict__ tgt, float* __restrict__ out) {

    __shared__ float sv[M];                        // v for this batch
    __shared__ __align__(16) char sbuf[16 * M * 2];// 32KB union: stage / sacc
    __shared__ float suAll[RPB];                   // scaled u' for block's rows
    __shared__ float ssrc[RPB];                    // src + 1e-12, cached
    __shared__ float schg[16];

    __half (*stage)[M] = (__half(*)[M])sbuf;       // [16][1024] halves (32KB)
    float  (*sacc)[M]  = (float (*)[M])sbuf;       // [4][1024] floats (16KB)

    const int t    = threadIdx.x;
    const int w    = t >> 5;
    const int lane = t & 31;
    const int blk  = blockIdx.x;
    const int b    = blk >> 3;
    const int sl   = blk & 7;
    const int rowBase = (b << 10) + (sl << 7);
    const size_t elemBase = (size_t)rowBase << 10;
    const int cg = t & 127, rs = t >> 7;

    const float4* sv4 = (const float4*)sv;

    if (t < RPB) ssrc[t] = __ldg(src + rowBase + t) + 1e-12f;
    __syncthreads();

    float accv[8];
    #pragma unroll
    for (int j = 0; j < 8; ++j) accv[j] = 0.f;
    float chm = 0.f;

    // ---- prologue: conversion fused with u1 + iteration-0 col acc ----
    {
        const float4* Cb = (const float4*)(cost + elemBase);
        for (int g = 0; g < 8; ++g) {              // 16-row groups
            int r = (g << 4) + w;                  // warp w owns row r (16 warps)
            const float4* Cr = Cb + ((size_t)r << 8);
            uint4* Kw = (uint4*)(g_K16 + elemBase + ((size_t)r << 10));
            uint4* Sw = (uint4*)stage[w];
            float s = 0.f;
            #pragma unroll
            for (int i = 0; i < 4; ++i) {
                int idx = i * 32 + lane;
                float4 c0 = __ldcs(&Cr[2 * idx]);
                float4 c1 = __ldcs(&Cr[2 * idx + 1]);
                float f0 = __expf(fmaf(c0.x, -20.f, 10.5f));
                float f1 = __expf(fmaf(c0.y, -20.f, 10.5f));
                float f2 = __expf(fmaf(c0.z, -20.f, 10.5f));
                float f3 = __expf(fmaf(c0.w, -20.f, 10.5f));
                float f4 = __expf(fmaf(c1.x, -20.f, 10.5f));
                float f5 = __expf(fmaf(c1.y, -20.f, 10.5f));
                float f6 = __expf(fmaf(c1.z, -20.f, 10.5f));
                float f7 = __expf(fmaf(c1.w, -20.f, 10.5f));
                s += ((f0 + f1) + (f2 + f3)) + ((f4 + f5) + (f6 + f7));
                __half2 h0 = __floats2half2_rn(f0, f1);
                __half2 h1 = __floats2half2_rn(f2, f3);
                __half2 h2 = __floats2half2_rn(f4, f5);
                __half2 h3 = __floats2half2_rn(f6, f7);
                uint4 pk;
                pk.x = *(unsigned*)&h0; pk.y = *(unsigned*)&h1;
                pk.z = *(unsigned*)&h2; pk.w = *(unsigned*)&h3;
                Kw[idx] = pk;
                Sw[idx] = pk;
            }
            #pragma unroll
            for (int o = 16; o; o >>= 1) s += __shfl_xor_sync(~0u, s, o);
            if (lane == 0) {
                float nu = ssrc[r] / s;            // v0 = 1 => rowdot = rowsum
                suAll[r] = nu;
                chm = fmaxf(chm, fabsf(logf(nu / EM105)));
            }
            __syncthreads();
            // it-0 col acc from staged halves (bit-identical to K16)
            #pragma unroll
            for (int j = 0; j < 4; ++j) {
                int rr = (rs << 2) + j;
                uint4 kq = ((const uint4*)stage[rr])[cg];
                float uu = suAll[(g << 4) + rr];
                float2 a  = __half22float2(*(__half2*)&kq.x);
                float2 bb = __half22float2(*(__half2*)&kq.y);
                float2 cc = __half22float2(*(__half2*)&kq.z);
                float2 dd = __half22float2(*(__half2*)&kq.w);
                accv[0] = fmaf(a.x,  uu, accv[0]);
                accv[1] = fmaf(a.y,  uu, accv[1]);
                accv[2] = fmaf(bb.x, uu, accv[2]);
                accv[3] = fmaf(bb.y, uu, accv[3]);
                accv[4] = fmaf(cc.x, uu, accv[4]);
                accv[5] = fmaf(cc.y, uu, accv[5]);
                accv[6] = fmaf(dd.x, uu, accv[6]);
                accv[7] = fmaf(dd.y, uu, accv[7]);
            }
            __syncthreads();
        }
    }

    unsigned gen = 0;

    for (int it = 0; it < MAX_ITER; ++it) {
        if (it > 0) {
            #pragma unroll
            for (int j = 0; j < 8; ++j) accv[j] = 0.f;
            chm = 0.f;

            #pragma unroll
            for (int g = 0; g < 4; ++g) {          // 32-row groups
                // --- row dots: warp w handles rows r0, r0+1 ---
                int r0 = (g << 5) + (w << 1);
                const uint4* K0 = (const uint4*)g_K16
                                  + ((size_t)(rowBase + r0) << 7);
                float s0 = 0.f, s1 = 0.f;
                #pragma unroll
                for (int i = 0; i < 4; ++i) {
                    int ci = i * 32 + lane;
                    uint4 ka = K0[ci], kb = K0[128 + ci];
                    float4 va = sv4[2 * ci], vb = sv4[2 * ci + 1];
                    s0 += dot8(ka, va, vb);
                    s1 += dot8(kb, va, vb);
                }
                #pragma unroll
                for (int o = 16; o; o >>= 1) {
                    s0 += __shfl_xor_sync(~0u, s0, o);
                    s1 += __shfl_xor_sync(~0u, s1, o);
                }
                if (lane == 0) {
                    float o0 = suAll[r0], o1 = suAll[r0 + 1];
                    float n0 = ssrc[r0]     / s0;
                    float n1 = ssrc[r0 + 1] / s1;
                    suAll[r0] = n0; suAll[r0 + 1] = n1;
                    chm = fmaxf(chm,
                          fmaxf(fabsf(logf(n0 / o0)), fabsf(logf(n1 / o1))));
                }
                __syncthreads();
                // --- col acc: thread (cg,rs): cols cg*8..+7 over 8 rows (L1) ---
                {
                    int rr0 = (g << 5) + (rs << 3);
                    const uint4* Kc = (const uint4*)g_K16
                        + ((size_t)(rowBase + rr0) << 7) + cg;
                    #pragma unroll
                    for (int j = 0; j < 8; ++j) {
                        uint4 kq = Kc[(size_t)j << 7];
                        float uu = suAll[rr0 + j];
                        float2 a  = __half22float2(*(__half2*)&kq.x);
                        float2 bb = __half22float2(*(__half2*)&kq.y);
                        float2 cc = __half22float2(*(__half2*)&kq.z);
                        float2 dd = __half22float2(*(__half2*)&kq.w);
                        accv[0] = fmaf(a.x,  uu, accv[0]);
                        accv[1] = fmaf(a.y,  uu, accv[1]);
                        accv[2] = fmaf(bb.x, uu, accv[2]);
                        accv[3] = fmaf(bb.y, uu, accv[3]);
                        accv[4] = fmaf(cc.x, uu, accv[4]);
                        accv[5] = fmaf(cc.y, uu, accv[5]);
                        accv[6] = fmaf(dd.x, uu, accv[6]);
                        accv[7] = fmaf(dd.y, uu, accv[7]);
                    }
                }
            }
        }

        // ---- tail: stage partials, combine (float2), publish change ----
        #pragma unroll
        for (int j = 0; j < 8; ++j) sacc[rs][cg * 8 + j] = accv[j];
        if (lane == 0) schg[w] = chm;
        __syncthreads();
        {
            float2* pp = (float2*)(g_partial
                + ((size_t)(it & 1) * GRID + blk) * M);
            const float2* s0p = (const float2*)sacc[0];
            const float2* s1p = (const float2*)sacc[1];
            const float2* s2p = (const float2*)sacc[2];
            const float2* s3p = (const float2*)sacc[3];
            float2 x0 = s0p[t], x1 = s1p[t], x2 = s2p[t], x3 = s3p[t];
            pp[t] = make_float2((x0.x + x1.x) + (x2.x + x3.x),
                                (x0.y + x1.y) + (x2.y + x3.y));
        }
        if (t == 0) {
            float m = schg[0];
            #pragma unroll
            for (int i = 1; i < 16; ++i) m = fmaxf(m, schg[i]);
            atomicMax(&g_change[it], __float_as_int(m));
        }

        gridBarrier(b, gen); ++gen;

        // ---- v-phase: every block of batch b builds full v (float2) ----
        {
            const float2* pb = (const float2*)(g_partial
                + ((size_t)(it & 1) * GRID + (b << 3)) * M);
            float2 ssum = make_float2(0.f, 0.f);
            #pragma unroll
            for (int k = 0; k < 8; ++k) {
                float2 x = __ldcg(pb + k * 512 + t);
                ssum.x += x.x; ssum.y += x.y;
            }
            float2 tg = __ldg((const float2*)(tgt + (b << 10)) + t);
            ((float2*)sv)[t] = make_float2((tg.x + 1e-12f) / ssum.x,
                                           (tg.y + 1e-12f) / ssum.y);
        }
        float ch = __int_as_float(*(volatile int*)&g_change[it]);
        __syncthreads();            // sv complete before next iter / epilogue
        if (ch < TOL) break;        // uniform across grid
    }

    // ---- epilogue: T = u' * K16 * v (K16 from L2, streaming stores) ----
    {
        const uint4* Kr = (const uint4*)(g_K16 + elemBase);
        float4* Ow = (float4*)(out + elemBase);
        #pragma unroll 2
        for (int k = 0; k < 32; ++k) {
            int i = k * TPB + t;                   // uint4 idx in 128x1024 slice
            uint4 kq = Kr[i];
            float u = suAll[i >> 7];
            float4 va = sv4[(i & 127) * 2], vb = sv4[(i & 127) * 2 + 1];
            float2 f0 = __half22float2(*(__half2*)&kq.x);
            float2 f1 = __half22float2(*(__half2*)&kq.y);
            float2 f2 = __half22float2(*(__half2*)&kq.z);
            float2 f3 = __half22float2(*(__half2*)&kq.w);
            float4 o0, o1;
            o0.x = u * f0.x * va.x;
            o0.y = u * f0.y * va.y;
            o0.z = u * f1.x * va.z;
            o0.w = u * f1.y * va.w;
            o1.x = u * f2.x * vb.x;
            o1.y = u * f2.y * vb.y;
            o1.z = u * f3.x * vb.z;
            o1.w = u * f3.y * vb.w;
            __stcs(Ow + 2 * i,     o0);
            __stcs(Ow + 2 * i + 1, o1);
        }
    }
}

// ---------------------------------------------------------------------------
extern "C" void kernel_launch(void* const* d_in, const int* in_sizes, int n_in,
                              void* d_out, int out_size) {
    const float* cost = (const float*)d_in[0];
    const float* src  = (const float*)d_in[1];
    const float* tgt  = (const float*)d_in[2];
    float* out = (float*)d_out;

    initKernel<<<1, 256>>>();
    sinkhornKernel<<<GRID, TPB>>>(cost, src, tgt, out);
}

// round 16
// speedup vs baseline: 1.0572x; 1.0261x over previous
#include <cuda_runtime.h>
#include <cuda_fp16.h>
#include <cstdint>

#define B 32
#define N 1024
#define M 1024
#define TOL 0.001f
#define MAX_ITER 50
#define GRID 256               // 8 blocks/batch; 2 blocks/SM co-resident
#define TPB 512
#define RPB 128                // rows per block
#define EM105 2.7536449349747158e-5f   // exp(-10.5): scaled-u init (log_u0 = 0)

// ---------------------------------------------------------------------------
__device__ __half   g_K16[(size_t)B * N * M];    // 64 MB: e^10.5*exp(-20c), L2-resident
__device__ float    g_partial[2 * GRID * M];     // double-buffered col partials
__device__ int      g_change[MAX_ITER];          // per-iter max |dlog u| (float bits)
__device__ unsigned g_batArrive[B * 32];         // per-batch arrival (1 line each)
__device__ unsigned g_barCount;                  // batch-leader count
__device__ unsigned g_barGen;                    // release generation

__global__ void initKernel() {
    int i = threadIdx.x;
    for (int k = i; k < MAX_ITER; k += 256) g_change[k] = 0;
    for (int k = i; k < B * 32; k += 256) g_batArrive[k] = 0u;
    if (i == 0) { g_barCount = 0u; g_barGen = 0u; }
}

__device__ __forceinline__ float dot8(uint4 kq, float4 va, float4 vb) {
    float2 f0 = __half22float2(*(__half2*)&kq.x);
    float2 f1 = __half22float2(*(__half2*)&kq.y);
    float2 f2 = __half22float2(*(__half2*)&kq.z);
    float2 f3 = __half22float2(*(__half2*)&kq.w);
    return f0.x*va.x + f0.y*va.y + f1.x*va.z + f1.y*va.w
         + f2.x*vb.x + f2.y*vb.y + f3.x*vb.z + f3.y*vb.w;
}

// Hierarchical grid barrier: 8 arrivals/batch line -> 32 leaders -> release.
__device__ __forceinline__ void gridBarrier(int b, unsigned gen) {
    __syncthreads();
    if (threadIdx.x == 0) {
        __threadfence();
        unsigned a = atomicAdd(&g_batArrive[b * 32], 1u);
        if (a == 7u) {
            atomicExch(&g_batArrive[b * 32], 0u);
            unsigned g = atomicAdd(&g_barCount, 1u);
            if (g == (unsigned)(B - 1)) {
                atomicExch(&g_barCount, 0u);
                __threadfence();
                atomicExch(&g_barGen, gen + 1u);
            }
        }
        while (*(volatile unsigned*)&g_barGen < gen + 1u) __nanosleep(32);
        __threadfence();
    }
    __syncthreads();
}

// ---------------------------------------------------------------------------
// Persistent fused Sinkhorn.
//  prologue: convert cost->K16 (MUFU expf) per 16-row group with smem staging;
//            computes u1 per row (shuffle sum, v0=1) AND iteration-0 col acc.
//  it>=1:    2 x 64-row groups: row dots with 4-row sv sharing (L2), then
//            col acc (L1/L2). 2 syncs per sweep.
//  tail:     stage col partials -> block partial -> 1 grid barrier -> v -> check.
//  epilogue: T = u' * K16 * v (hoisted v, streaming stores).
// ---------------------------------------------------------------------------
__global__ void __launch_bounds__(TPB, 2) sinkhornKernel(
    const float* __restrict__ cost, const float* __restrict__ src,
    const float* __restrict__ tgt, float* __restrict__ out) {

    __shared__ float sv[M];                        // v for this batch
    __shared__ __align__(16) char sbuf[16 * M * 2];// 32KB union: stage / sacc
    __shared__ float suAll[RPB];                   // scaled u' for block's rows
    __shared__ float ssrc[RPB];                    // src + 1e-12, cached
    __shared__ float schg[16];

    __half (*stage)[M] = (__half(*)[M])sbuf;       // [16][1024] halves (32KB)
    float  (*sacc)[M]  = (float (*)[M])sbuf;       // [4][1024] floats (16KB)

    const int t    = threadIdx.x;
    const int w    = t >> 5;
    const int lane = t & 31;
    const int blk  = blockIdx.x;
    const int b    = blk >> 3;
    const int sl   = blk & 7;
    const int rowBase = (b << 10) + (sl << 7);
    const size_t elemBase = (size_t)rowBase << 10;
    const int cg = t & 127, rs = t >> 7;

    const float4* sv4 = (const float4*)sv;

    if (t < RPB) ssrc[t] = __ldg(src + rowBase + t) + 1e-12f;
    __syncthreads();

    float accv[8];
    #pragma unroll
    for (int j = 0; j < 8; ++j) accv[j] = 0.f;
    float chm = 0.f;

    // ---- prologue: conversion fused with u1 + iteration-0 col acc ----
    {
        const float4* Cb = (const float4*)(cost + elemBase);
        for (int g = 0; g < 8; ++g) {              // 16-row groups
            int r = (g << 4) + w;                  // warp w owns row r (16 warps)
            const float4* Cr = Cb + ((size_t)r << 8);
            uint4* Kw = (uint4*)(g_K16 + elemBase + ((size_t)r << 10));
            uint4* Sw = (uint4*)stage[w];
            float s = 0.f;
            #pragma unroll
            for (int i = 0; i < 4; ++i) {
                int idx = i * 32 + lane;
                float4 c0 = __ldcs(&Cr[2 * idx]);
                float4 c1 = __ldcs(&Cr[2 * idx + 1]);
                float f0 = __expf(fmaf(c0.x, -20.f, 10.5f));
                float f1 = __expf(fmaf(c0.y, -20.f, 10.5f));
                float f2 = __expf(fmaf(c0.z, -20.f, 10.5f));
                float f3 = __expf(fmaf(c0.w, -20.f, 10.5f));
                float f4 = __expf(fmaf(c1.x, -20.f, 10.5f));
                float f5 = __expf(fmaf(c1.y, -20.f, 10.5f));
                float f6 = __expf(fmaf(c1.z, -20.f, 10.5f));
                float f7 = __expf(fmaf(c1.w, -20.f, 10.5f));
                s += ((f0 + f1) + (f2 + f3)) + ((f4 + f5) + (f6 + f7));
                __half2 h0 = __floats2half2_rn(f0, f1);
                __half2 h1 = __floats2half2_rn(f2, f3);
                __half2 h2 = __floats2half2_rn(f4, f5);
                __half2 h3 = __floats2half2_rn(f6, f7);
                uint4 pk;
                pk.x = *(unsigned*)&h0; pk.y = *(unsigned*)&h1;
                pk.z = *(unsigned*)&h2; pk.w = *(unsigned*)&h3;
                Kw[idx] = pk;
                Sw[idx] = pk;
            }
            #pragma unroll
            for (int o = 16; o; o >>= 1) s += __shfl_xor_sync(~0u, s, o);
            if (lane == 0) {
                float nu = ssrc[r] / s;            // v0 = 1 => rowdot = rowsum
                suAll[r] = nu;
                chm = fmaxf(chm, fabsf(logf(nu / EM105)));
            }
            __syncthreads();
            // it-0 col acc from staged halves (bit-identical to K16)
            #pragma unroll
            for (int j = 0; j < 4; ++j) {
                int rr = (rs << 2) + j;
                uint4 kq = ((const uint4*)stage[rr])[cg];
                float uu = suAll[(g << 4) + rr];
                float2 a  = __half22float2(*(__half2*)&kq.x);
                float2 bb = __half22float2(*(__half2*)&kq.y);
                float2 cc = __half22float2(*(__half2*)&kq.z);
                float2 dd = __half22float2(*(__half2*)&kq.w);
                accv[0] = fmaf(a.x,  uu, accv[0]);
                accv[1] = fmaf(a.y,  uu, accv[1]);
                accv[2] = fmaf(bb.x, uu, accv[2]);
                accv[3] = fmaf(bb.y, uu, accv[3]);
                accv[4] = fmaf(cc.x, uu, accv[4]);
                accv[5] = fmaf(cc.y, uu, accv[5]);
                accv[6] = fmaf(dd.x, uu, accv[6]);
                accv[7] = fmaf(dd.y, uu, accv[7]);
            }
            __syncthreads();
        }
    }

    unsigned gen = 0;

    for (int it = 0; it < MAX_ITER; ++it) {
        if (it > 0) {
            #pragma unroll
            for (int j = 0; j < 8; ++j) accv[j] = 0.f;
            chm = 0.f;

            #pragma unroll
            for (int g = 0; g < 2; ++g) {          // 64-row groups
                // --- row dots: warp w owns rows r0..r0+3, shares sv reads ---
                int r0 = (g << 6) + (w << 2);
                const uint4* K0 = (const uint4*)g_K16
                                  + ((size_t)(rowBase + r0) << 7);
                float s0 = 0.f, s1 = 0.f, s2 = 0.f, s3 = 0.f;
                #pragma unroll
                for (int i = 0; i < 4; ++i) {
                    int ci = i * 32 + lane;
                    uint4 ka = K0[ci];
                    uint4 kb = K0[128 + ci];
                    uint4 kc = K0[256 + ci];
                    uint4 kd = K0[384 + ci];
                    float4 va = sv4[2 * ci], vb = sv4[2 * ci + 1];
                    s0 += dot8(ka, va, vb);
                    s1 += dot8(kb, va, vb);
                    s2 += dot8(kc, va, vb);
                    s3 += dot8(kd, va, vb);
                }
                #pragma unroll
                for (int o = 16; o; o >>= 1) {
                    s0 += __shfl_xor_sync(~0u, s0, o);
                    s1 += __shfl_xor_sync(~0u, s1, o);
                    s2 += __shfl_xor_sync(~0u, s2, o);
                    s3 += __shfl_xor_sync(~0u, s3, o);
                }
                if (lane == 0) {
                    float ss[4] = {s0, s1, s2, s3};
                    #pragma unroll
                    for (int j = 0; j < 4; ++j) {
                        float old = suAll[r0 + j];
                        float nu  = ssrc[r0 + j] / ss[j];
                        suAll[r0 + j] = nu;
                        chm = fmaxf(chm, fabsf(logf(nu / old)));
                    }
                }
                __syncthreads();
                // --- col acc: thread (cg,rs): cols cg*8..+7 over 16 rows ---
                {
                    int rr0 = (g << 6) + (rs << 4);
                    const uint4* Kc = (const uint4*)g_K16
                        + ((size_t)(rowBase + rr0) << 7) + cg;
                    #pragma unroll
                    for (int j = 0; j < 16; ++j) {
                        uint4 kq = Kc[(size_t)j << 7];
                        float uu = suAll[rr0 + j];
                        float2 a  = __half22float2(*(__half2*)&kq.x);
                        float2 bb = __half22float2(*(__half2*)&kq.y);
                        float2 cc = __half22float2(*(__half2*)&kq.z);
                        float2 dd = __half22float2(*(__half2*)&kq.w);
                        accv[0] = fmaf(a.x,  uu, accv[0]);
                        accv[1] = fmaf(a.y,  uu, accv[1]);
                        accv[2] = fmaf(bb.x, uu, accv[2]);
                        accv[3] = fmaf(bb.y, uu, accv[3]);
                        accv[4] = fmaf(cc.x, uu, accv[4]);
                        accv[5] = fmaf(cc.y, uu, accv[5]);
                        accv[6] = fmaf(dd.x, uu, accv[6]);
                        accv[7] = fmaf(dd.y, uu, accv[7]);
                    }
                }
                // no sync needed: next group's suAll writes are disjoint rows
            }
        }

        // ---- tail: stage partials, combine (float2), publish change ----
        __syncthreads();           // col acc done before sacc overwrite
        #pragma unroll
        for (int j = 0; j < 8; ++j) sacc[rs][cg * 8 + j] = accv[j];
        if (lane == 0) schg[w] = chm;
        __syncthreads();
        {
            float2* pp = (float2*)(g_partial
                + ((size_t)(it & 1) * GRID + blk) * M);
            const float2* s0p = (const float2*)sacc[0];
            const float2* s1p = (const float2*)sacc[1];
            const float2* s2p = (const float2*)sacc[2];
            const float2* s3p = (const float2*)sacc[3];
            float2 x0 = s0p[t], x1 = s1p[t], x2 = s2p[t], x3 = s3p[t];
            pp[t] = make_float2((x0.x + x1.x) + (x2.x + x3.x),
                                (x0.y + x1.y) + (x2.y + x3.y));
        }
        if (t == 0) {
            float m = schg[0];
            #pragma unroll
            for (int i = 1; i < 16; ++i) m = fmaxf(m, schg[i]);
            atomicMax(&g_change[it], __float_as_int(m));
        }

        gridBarrier(b, gen); ++gen;

        // ---- v-phase: every block of batch b builds full v (float2) ----
        {
            const float2* pb = (const float2*)(g_partial
                + ((size_t)(it & 1) * GRID + (b << 3)) * M);
            float2 ssum = make_float2(0.f, 0.f);
            #pragma unroll
            for (int k = 0; k < 8; ++k) {
                float2 x = __ldcg(pb + k * 512 + t);
                ssum.x += x.x; ssum.y += x.y;
            }
            float2 tg = __ldg((const float2*)(tgt + (b << 10)) + t);
            ((float2*)sv)[t] = make_float2((tg.x + 1e-12f) / ssum.x,
                                           (tg.y + 1e-12f) / ssum.y);
        }
        float ch = __int_as_float(*(volatile int*)&g_change[it]);
        __syncthreads();            // sv complete before next iter / epilogue
        if (ch < TOL) break;        // uniform across grid
    }

    // ---- epilogue: T = u' * K16 * v (v hoisted, streaming stores) ----
    {
        const uint4* Kr = (const uint4*)(g_K16 + elemBase);
        float4* Ow = (float4*)(out + elemBase);
        const int tc = t & 127;                    // i & 127 == t & 127, const
        const float4 va = sv4[2 * tc], vb = sv4[2 * tc + 1];
        #pragma unroll 2
        for (int k = 0; k < 32; ++k) {
            int i = k * TPB + t;                   // uint4 idx in 128x1024 slice
            uint4 kq = Kr[i];
            float u = suAll[i >> 7];
            float2 f0 = __half22float2(*(__half2*)&kq.x);
            float2 f1 = __half22float2(*(__half2*)&kq.y);
            float2 f2 = __half22float2(*(__half2*)&kq.z);
            float2 f3 = __half22float2(*(__half2*)&kq.w);
            float4 o0, o1;
            o0.x = u * f0.x * va.x;
            o0.y = u * f0.y * va.y;
            o0.z = u * f1.x * va.z;
            o0.w = u * f1.y * va.w;
            o1.x = u * f2.x * vb.x;
            o1.y = u * f2.y * vb.y;
            o1.z = u * f3.x * vb.z;
            o1.w = u * f3.y * vb.w;
            __stcs(Ow + 2 * i,     o0);
            __stcs(Ow + 2 * i + 1, o1);
        }
    }
}

// ---------------------------------------------------------------------------
extern "C" void kernel_launch(void* const* d_in, const int* in_sizes, int n_in,
                              void* d_out, int out_size) {
    const float* cost = (const float*)d_in[0];
    const float* src  = (const float*)d_in[1];
    const float* tgt  = (const float*)d_in[2];
    float* out = (float*)d_out;

    initKernel<<<1, 256>>>();
    sinkhornKernel<<<GRID, TPB>>>(cost, src, tgt, out);
}